// round 3
// baseline (speedup 1.0000x reference)
#include <cuda_runtime.h>
#include <cuda_bf16.h>

// Problem constants
#define N_ROWS 16384
#define SPLIT  100
#define IDIM   128
#define NH     4
#define PD     64
#define OUTD   (NH * PD)        // 256
#define ITERS  (SPLIT / 2)      // 50: 2 segments per iteration (one per half-warp)
#define NWARP  4                // warps (rows) per block

// wq[h][i] = sum_o W[h,i,o] * q[h,o]  — precomputed by a tiny kernel
__device__ float g_wq[NH * IDIM];

__global__ void wq_kernel(const float* __restrict__ W, const float* __restrict__ q) {
    int idx = threadIdx.x;                     // 512 threads
    if (idx >= NH * IDIM) return;
    int h = idx >> 7, i = idx & 127;
    const float* Wr = W + ((size_t)(h * IDIM + i)) * PD;
    const float* qr = q + h * PD;
    float acc = 0.f;
#pragma unroll
    for (int o = 0; o < PD; o++) acc = fmaf(Wr[o], qr[o], acc);
    g_wq[idx] = acc;
}

__global__ void __launch_bounds__(NWARP * 32)
attn_kernel(const float* __restrict__ x, const float* __restrict__ W,
            float* __restrict__ out) {
    // epilogue staging only: per-warp 512 floats (normalized xbar, 4 heads x 128)
    __shared__ float sxbar[NWARP][NH * IDIM];   // 8 KB

    const int warp = threadIdx.x >> 5;
    const int lane = threadIdx.x & 31;
    const int half = lane >> 4;                 // which of the 2 segments this iter
    const int p16  = lane & 15;                 // owns i in [p16*8, p16*8+8) of its segment
    const int row  = blockIdx.x * NWARP + warp; // grid sized exactly: always < N_ROWS
    // lane's fixed offset within each 256-float (2-segment) chunk
    const float* xp = x + (size_t)row * (SPLIT * IDIM) + half * IDIM + p16 * 8;

    // wq fragment for this lane's 8 i-values, all 4 heads (registers)
    float4 wq0[NH], wq1[NH];
#pragma unroll
    for (int h = 0; h < NH; h++) {
        const float4* g = (const float4*)(g_wq + h * IDIM + p16 * 8);
        wq0[h] = g[0];
        wq1[h] = g[1];
    }

    // accumulators: unnormalized weighted x (this lane's 8 i's, per head) + denom
    float4 xb0[NH], xb1[NH];
    float dsum[NH];
#pragma unroll
    for (int h = 0; h < NH; h++) {
        xb0[h] = make_float4(0.f, 0.f, 0.f, 0.f);
        xb1[h] = make_float4(0.f, 0.f, 0.f, 0.f);
        dsum[h] = 0.f;
    }

    // software pipeline: prefetch iteration 0
    float4 n0 = ((const float4*)xp)[0];
    float4 n1 = ((const float4*)xp)[1];

    for (int it = 0; it < ITERS; it++) {
        float4 xv0 = n0;
        float4 xv1 = n1;
        // prefetch next iteration (256 floats further along the row)
        if (it + 1 < ITERS) {
            const float4* src = (const float4*)(xp + (it + 1) * 256);
            n0 = src[0];
            n1 = src[1];
        }

        // partial scores for this lane's segment, all heads
        float p[NH];
#pragma unroll
        for (int h = 0; h < NH; h++) {
            float a;
            a = xv0.x * wq0[h].x;
            a = fmaf(xv0.y, wq0[h].y, a);
            a = fmaf(xv0.z, wq0[h].z, a);
            a = fmaf(xv0.w, wq0[h].w, a);
            a = fmaf(xv1.x, wq1[h].x, a);
            a = fmaf(xv1.y, wq1[h].y, a);
            a = fmaf(xv1.z, wq1[h].z, a);
            a = fmaf(xv1.w, wq1[h].w, a);
            p[h] = a;
        }
        // reduce within the 16-lane half (xor offsets stay inside the half)
#pragma unroll
        for (int off = 8; off >= 1; off >>= 1) {
#pragma unroll
            for (int h = 0; h < NH; h++)
                p[h] += __shfl_xor_sync(0xffffffffu, p[h], off);
        }
        // leaky_relu -> exp (no max subtraction: |score| <~ 15 << 88, fp32-safe)
#pragma unroll
        for (int h = 0; h < NH; h++) {
            float s = fmaxf(p[h], 0.2f * p[h]);
            float e = __expf(s);
            dsum[h] += e;
            xb0[h].x = fmaf(e, xv0.x, xb0[h].x);
            xb0[h].y = fmaf(e, xv0.y, xb0[h].y);
            xb0[h].z = fmaf(e, xv0.z, xb0[h].z);
            xb0[h].w = fmaf(e, xv0.w, xb0[h].w);
            xb1[h].x = fmaf(e, xv1.x, xb1[h].x);
            xb1[h].y = fmaf(e, xv1.y, xb1[h].y);
            xb1[h].z = fmaf(e, xv1.z, xb1[h].z);
            xb1[h].w = fmaf(e, xv1.w, xb1[h].w);
        }
    }

    // combine the two halves (they handled even/odd segments)
#pragma unroll
    for (int h = 0; h < NH; h++) {
        dsum[h] += __shfl_xor_sync(0xffffffffu, dsum[h], 16);
        xb0[h].x += __shfl_xor_sync(0xffffffffu, xb0[h].x, 16);
        xb0[h].y += __shfl_xor_sync(0xffffffffu, xb0[h].y, 16);
        xb0[h].z += __shfl_xor_sync(0xffffffffu, xb0[h].z, 16);
        xb0[h].w += __shfl_xor_sync(0xffffffffu, xb0[h].w, 16);
        xb1[h].x += __shfl_xor_sync(0xffffffffu, xb1[h].x, 16);
        xb1[h].y += __shfl_xor_sync(0xffffffffu, xb1[h].y, 16);
        xb1[h].z += __shfl_xor_sync(0xffffffffu, xb1[h].z, 16);
        xb1[h].w += __shfl_xor_sync(0xffffffffu, xb1[h].w, 16);
    }

    // stage normalized xbar into shared: lanes of half 0 hold the full sums
    float* sx = &sxbar[warp][0];
    if (half == 0) {
#pragma unroll
        for (int h = 0; h < NH; h++) {
            float inv = 1.0f / dsum[h];
            float4 v0 = xb0[h], v1 = xb1[h];
            v0.x *= inv; v0.y *= inv; v0.z *= inv; v0.w *= inv;
            v1.x *= inv; v1.y *= inv; v1.z *= inv; v1.w *= inv;
            float4* dst = (float4*)(sx + h * IDIM + p16 * 8);
            dst[0] = v0;
            dst[1] = v1;
        }
    }
    __syncwarp();

    // epilogue GEMV: pooled[h,o] = sum_i xbarN[h,i] * W[h,i,o]
    // lane -> head h2 = lane>>3, two float4 o-blocks at cb*8 and cb*8+4
    const int h2 = lane >> 3;
    const int cb = lane & 7;
    const float4* Wv = (const float4*)W + (size_t)h2 * IDIM * (PD / 4) + cb * 2;
    const float* sxh = sx + h2 * IDIM;
    float4 a0 = make_float4(0.f, 0.f, 0.f, 0.f);
    float4 a1 = make_float4(0.f, 0.f, 0.f, 0.f);
#pragma unroll 8
    for (int i = 0; i < IDIM; i++) {
        float xv = sxh[i];                       // broadcast within 8-lane group
        float4 w0 = Wv[i * (PD / 4)];
        float4 w1 = Wv[i * (PD / 4) + 1];
        a0.x = fmaf(xv, w0.x, a0.x);
        a0.y = fmaf(xv, w0.y, a0.y);
        a0.z = fmaf(xv, w0.z, a0.z);
        a0.w = fmaf(xv, w0.w, a0.w);
        a1.x = fmaf(xv, w1.x, a1.x);
        a1.y = fmaf(xv, w1.y, a1.y);
        a1.z = fmaf(xv, w1.z, a1.z);
        a1.w = fmaf(xv, w1.w, a1.w);
    }
    float4* op = (float4*)(out + (size_t)row * OUTD + h2 * PD + cb * 8);
    op[0] = a0;
    op[1] = a1;
}

extern "C" void kernel_launch(void* const* d_in, const int* in_sizes, int n_in,
                              void* d_out, int out_size) {
    // metadata order: x [N, 12800], W [4,128,64], q [4,64] — identify defensively by size
    const float* x = (const float*)d_in[0];
    const float* W = (const float*)d_in[1];
    const float* q = (const float*)d_in[2];
    for (int i = 0; i < n_in && i < 3; i++) {
        if (in_sizes[i] == N_ROWS * SPLIT * IDIM) x = (const float*)d_in[i];
        else if (in_sizes[i] == NH * IDIM * PD)   W = (const float*)d_in[i];
        else if (in_sizes[i] == NH * PD)          q = (const float*)d_in[i];
    }
    float* out = (float*)d_out;

    wq_kernel<<<1, 512>>>(W, q);
    attn_kernel<<<N_ROWS / NWARP, NWARP * 32>>>(x, W, out);
}

// round 4
// speedup vs baseline: 1.2994x; 1.2994x over previous
#include <cuda_runtime.h>
#include <cuda_bf16.h>

// Problem constants
#define N_ROWS 16384
#define SPLIT  100
#define IDIM   128
#define NH     4
#define PD     64
#define OUTD   (NH * PD)        // 256
#define ITERS  (SPLIT / 2)      // 50: 2 segments per iteration (one per half-warp)
#define SLOTS  8                // cp.async ring slots (1KB each)
#define PRE    6                // groups kept in flight (< SLOTS, so no read/write hazard)
#define NWARP  4                // warps (rows) per block

// wq[h][i] = sum_o W[h,i,o] * q[h,o]  — precomputed by a tiny kernel
__device__ float g_wq[NH * IDIM];

__global__ void wq_kernel(const float* __restrict__ W, const float* __restrict__ q) {
    int idx = threadIdx.x;                     // 512 threads
    if (idx >= NH * IDIM) return;
    int h = idx >> 7, i = idx & 127;
    const float* Wr = W + ((size_t)(h * IDIM + i)) * PD;
    const float* qr = q + h * PD;
    float acc = 0.f;
#pragma unroll
    for (int o = 0; o < PD; o++) acc = fmaf(Wr[o], qr[o], acc);
    g_wq[idx] = acc;
}

__device__ __forceinline__ void cp16(void* smem_dst, const void* gsrc) {
    unsigned saddr = (unsigned)__cvta_generic_to_shared(smem_dst);
    asm volatile("cp.async.cg.shared.global [%0], [%1], 16;\n" :: "r"(saddr), "l"(gsrc));
}
__device__ __forceinline__ void cp_commit() { asm volatile("cp.async.commit_group;\n"); }
__device__ __forceinline__ void cp_wait_pre() { asm volatile("cp.async.wait_group %0;\n" :: "n"(PRE - 1)); }

__global__ void __launch_bounds__(NWARP * 32)
attn_kernel(const float* __restrict__ x, const float* __restrict__ W,
            float* __restrict__ out) {
    // per-warp ring: SLOTS slots of 2 segments (256 floats = 64 float4 = 1KB)
    __shared__ float4 ring[NWARP][SLOTS][64];   // 32 KB

    const int warp = threadIdx.x >> 5;
    const int lane = threadIdx.x & 31;
    const int half = lane >> 4;                 // which of the 2 segments this iter
    const int p16  = lane & 15;                 // owns i in [p16*8, p16*8+8) of its segment
    const int row  = blockIdx.x * NWARP + warp; // grid sized exactly: always < N_ROWS
    const float* xrow = x + (size_t)row * (SPLIT * IDIM);

    // wq fragment for this lane's 8 i-values, all 4 heads (registers)
    float4 wq0[NH], wq1[NH];
#pragma unroll
    for (int h = 0; h < NH; h++) {
        const float4* g = (const float4*)(g_wq + h * IDIM + p16 * 8);
        wq0[h] = g[0];
        wq1[h] = g[1];
    }

    // accumulators: unnormalized weighted x (this lane's 8 i's, per head) + denom
    float4 xb0[NH], xb1[NH];
    float dsum[NH];
#pragma unroll
    for (int h = 0; h < NH; h++) {
        xb0[h] = make_float4(0.f, 0.f, 0.f, 0.f);
        xb1[h] = make_float4(0.f, 0.f, 0.f, 0.f);
        dsum[h] = 0.f;
    }

    // prologue: fill PRE pipeline stages (each iter = 1KB = 2 segments, contiguous)
#pragma unroll
    for (int it = 0; it < PRE; it++) {
        const float* src = xrow + it * 256 + lane * 8;
        cp16(&ring[warp][it][lane * 2],     src);
        cp16(&ring[warp][it][lane * 2 + 1], src + 4);
        cp_commit();
    }

    for (int it = 0; it < ITERS; it++) {
        cp_wait_pre();       // this thread's data for iteration `it` is complete
        __syncwarp();

        const int slot = it & (SLOTS - 1);
        // each lane reads back exactly the 32 bytes it cp'd itself:
        // dst index lane*2 == half*32 + p16*2
        float4 xv0 = ring[warp][slot][half * 32 + p16 * 2];
        float4 xv1 = ring[warp][slot][half * 32 + p16 * 2 + 1];

        // issue the next stage (write slot is distance 6 ahead of oldest live slot)
        const int nit = it + PRE;
        if (nit < ITERS) {
            const int ns = nit & (SLOTS - 1);
            const float* src = xrow + nit * 256 + lane * 8;
            cp16(&ring[warp][ns][lane * 2],     src);
            cp16(&ring[warp][ns][lane * 2 + 1], src + 4);
        }
        cp_commit();  // tail commits empty groups, keeping wait counts aligned

        // partial scores for this lane's segment, all heads
        float p[NH];
#pragma unroll
        for (int h = 0; h < NH; h++) {
            float a;
            a = xv0.x * wq0[h].x;
            a = fmaf(xv0.y, wq0[h].y, a);
            a = fmaf(xv0.z, wq0[h].z, a);
            a = fmaf(xv0.w, wq0[h].w, a);
            a = fmaf(xv1.x, wq1[h].x, a);
            a = fmaf(xv1.y, wq1[h].y, a);
            a = fmaf(xv1.z, wq1[h].z, a);
            a = fmaf(xv1.w, wq1[h].w, a);
            p[h] = a;
        }
        // reduce within the 16-lane half (xor offsets stay inside the half)
#pragma unroll
        for (int off = 8; off >= 1; off >>= 1) {
#pragma unroll
            for (int h = 0; h < NH; h++)
                p[h] += __shfl_xor_sync(0xffffffffu, p[h], off);
        }
        // leaky_relu -> exp (no max subtraction: |score| <~ 15 << 88, fp32-safe)
#pragma unroll
        for (int h = 0; h < NH; h++) {
            float s = fmaxf(p[h], 0.2f * p[h]);
            float e = __expf(s);
            dsum[h] += e;
            xb0[h].x = fmaf(e, xv0.x, xb0[h].x);
            xb0[h].y = fmaf(e, xv0.y, xb0[h].y);
            xb0[h].z = fmaf(e, xv0.z, xb0[h].z);
            xb0[h].w = fmaf(e, xv0.w, xb0[h].w);
            xb1[h].x = fmaf(e, xv1.x, xb1[h].x);
            xb1[h].y = fmaf(e, xv1.y, xb1[h].y);
            xb1[h].z = fmaf(e, xv1.z, xb1[h].z);
            xb1[h].w = fmaf(e, xv1.w, xb1[h].w);
        }
    }

    // combine the two halves (they handled even/odd segments)
#pragma unroll
    for (int h = 0; h < NH; h++) {
        dsum[h] += __shfl_xor_sync(0xffffffffu, dsum[h], 16);
        xb0[h].x += __shfl_xor_sync(0xffffffffu, xb0[h].x, 16);
        xb0[h].y += __shfl_xor_sync(0xffffffffu, xb0[h].y, 16);
        xb0[h].z += __shfl_xor_sync(0xffffffffu, xb0[h].z, 16);
        xb0[h].w += __shfl_xor_sync(0xffffffffu, xb0[h].w, 16);
        xb1[h].x += __shfl_xor_sync(0xffffffffu, xb1[h].x, 16);
        xb1[h].y += __shfl_xor_sync(0xffffffffu, xb1[h].y, 16);
        xb1[h].z += __shfl_xor_sync(0xffffffffu, xb1[h].z, 16);
        xb1[h].w += __shfl_xor_sync(0xffffffffu, xb1[h].w, 16);
    }

    // stage normalized xbar into (now-idle) ring space: 512 floats per warp
    float* sx = (float*)&ring[warp][0][0];
    __syncwarp();   // everyone done reading the ring
    if (half == 0) {
#pragma unroll
        for (int h = 0; h < NH; h++) {
            float inv = 1.0f / dsum[h];
            float4 v0 = xb0[h], v1 = xb1[h];
            v0.x *= inv; v0.y *= inv; v0.z *= inv; v0.w *= inv;
            v1.x *= inv; v1.y *= inv; v1.z *= inv; v1.w *= inv;
            float4* dst = (float4*)(sx + h * IDIM + p16 * 8);
            dst[0] = v0;
            dst[1] = v1;
        }
    }
    __syncwarp();

    // epilogue GEMV: pooled[h,o] = sum_i xbarN[h,i] * W[h,i,o]
    // lane -> head h2 = lane>>3, two float4 o-blocks at cb*8 and cb*8+4
    const int h2 = lane >> 3;
    const int cb = lane & 7;
    const float4* Wv = (const float4*)W + (size_t)h2 * IDIM * (PD / 4) + cb * 2;
    const float* sxh = sx + h2 * IDIM;
    float4 a0 = make_float4(0.f, 0.f, 0.f, 0.f);
    float4 a1 = make_float4(0.f, 0.f, 0.f, 0.f);
#pragma unroll 8
    for (int i = 0; i < IDIM; i++) {
        float xv = sxh[i];                       // broadcast within 8-lane group
        float4 w0 = Wv[i * (PD / 4)];
        float4 w1 = Wv[i * (PD / 4) + 1];
        a0.x = fmaf(xv, w0.x, a0.x);
        a0.y = fmaf(xv, w0.y, a0.y);
        a0.z = fmaf(xv, w0.z, a0.z);
        a0.w = fmaf(xv, w0.w, a0.w);
        a1.x = fmaf(xv, w1.x, a1.x);
        a1.y = fmaf(xv, w1.y, a1.y);
        a1.z = fmaf(xv, w1.z, a1.z);
        a1.w = fmaf(xv, w1.w, a1.w);
    }
    float4* op = (float4*)(out + (size_t)row * OUTD + h2 * PD + cb * 8);
    op[0] = a0;
    op[1] = a1;
}

extern "C" void kernel_launch(void* const* d_in, const int* in_sizes, int n_in,
                              void* d_out, int out_size) {
    // metadata order: x [N, 12800], W [4,128,64], q [4,64] — identify defensively by size
    const float* x = (const float*)d_in[0];
    const float* W = (const float*)d_in[1];
    const float* q = (const float*)d_in[2];
    for (int i = 0; i < n_in && i < 3; i++) {
        if (in_sizes[i] == N_ROWS * SPLIT * IDIM) x = (const float*)d_in[i];
        else if (in_sizes[i] == NH * IDIM * PD)   W = (const float*)d_in[i];
        else if (in_sizes[i] == NH * PD)          q = (const float*)d_in[i];
    }
    float* out = (float*)d_out;

    wq_kernel<<<1, 512>>>(W, q);
    attn_kernel<<<N_ROWS / NWARP, NWARP * 32>>>(x, W, out);
}

// round 6
// speedup vs baseline: 1.3860x; 1.0666x over previous
#include <cuda_runtime.h>
#include <cuda_bf16.h>

// Problem constants
#define N_ROWS 16384
#define SPLIT  100
#define IDIM   128
#define NH     4
#define PD     64
#define OUTD   (NH * PD)        // 256
#define ITERS  (SPLIT / 2)      // 50: 2 segments per iteration (one per half-warp)
#define SLOTS  8                // cp.async ring slots (1KB each)
#define PRE    6                // groups kept in flight (< SLOTS, so no read/write hazard)
#define NWARP  4                // warps (rows) per block

// wq[h][i] = sum_o W[h,i,o] * q[h,o]  — precomputed by a tiny kernel
__device__ float g_wq[NH * IDIM];

__global__ void wq_kernel(const float* __restrict__ W, const float* __restrict__ q) {
    int idx = threadIdx.x;                     // 512 threads
    if (idx >= NH * IDIM) return;
    int h = idx >> 7, i = idx & 127;
    const float* Wr = W + ((size_t)(h * IDIM + i)) * PD;
    const float* qr = q + h * PD;
    float acc = 0.f;
#pragma unroll
    for (int o = 0; o < PD; o++) acc = fmaf(Wr[o], qr[o], acc);
    g_wq[idx] = acc;
}

__device__ __forceinline__ void cp16(void* smem_dst, const void* gsrc) {
    unsigned saddr = (unsigned)__cvta_generic_to_shared(smem_dst);
    asm volatile("cp.async.cg.shared.global [%0], [%1], 16;\n" :: "r"(saddr), "l"(gsrc));
}
__device__ __forceinline__ void cp_commit() { asm volatile("cp.async.commit_group;\n"); }
__device__ __forceinline__ void cp_wait_pre() { asm volatile("cp.async.wait_group %0;\n" :: "n"(PRE - 1)); }

__global__ void __launch_bounds__(NWARP * 32)
attn_kernel(const float* __restrict__ x, const float* __restrict__ W,
            float* __restrict__ out) {
    // per-warp ring: SLOTS slots of 2 segments (256 floats = 64 float4 = 1KB)
    __shared__ float4 ring[NWARP][SLOTS][64];   // 32 KB

    const int warp = threadIdx.x >> 5;
    const int lane = threadIdx.x & 31;
    const int half = lane >> 4;                 // which of the 2 segments this iter
    const int p16  = lane & 15;                 // owns i in [p16*8, p16*8+8) of its segment
    const int b3   = (lane >> 3) & 1;           // specialization bits within the 16-half
    const int b2   = (lane >> 2) & 1;
    const int row  = blockIdx.x * NWARP + warp; // grid sized exactly: always < N_ROWS
    const float* xrow = x + (size_t)row * (SPLIT * IDIM);

    // wq fragment for this lane's 8 i-values, all 4 heads (registers)
    float4 wq0[NH], wq1[NH];
#pragma unroll
    for (int h = 0; h < NH; h++) {
        const float4* g = (const float4*)(g_wq + h * IDIM + p16 * 8);
        wq0[h] = g[0];
        wq1[h] = g[1];
    }

    // accumulators: unnormalized weighted x (this lane's 8 i's, per head) + denom
    float4 xb0[NH], xb1[NH];
    float dsum[NH];
#pragma unroll
    for (int h = 0; h < NH; h++) {
        xb0[h] = make_float4(0.f, 0.f, 0.f, 0.f);
        xb1[h] = make_float4(0.f, 0.f, 0.f, 0.f);
        dsum[h] = 0.f;
    }

    // prologue: fill PRE pipeline stages (each iter = 1KB = 2 segments, contiguous)
#pragma unroll
    for (int it = 0; it < PRE; it++) {
        const float* src = xrow + it * 256 + lane * 8;
        cp16(&ring[warp][it][lane * 2],     src);
        cp16(&ring[warp][it][lane * 2 + 1], src + 4);
        cp_commit();
    }

    for (int it = 0; it < ITERS; it++) {
        cp_wait_pre();       // this thread's data for iteration `it` is complete
        __syncwarp();

        const int slot = it & (SLOTS - 1);
        float4 xv0 = ring[warp][slot][half * 32 + p16 * 2];
        float4 xv1 = ring[warp][slot][half * 32 + p16 * 2 + 1];

        // issue the next stage
        const int nit = it + PRE;
        if (nit < ITERS) {
            const int ns = nit & (SLOTS - 1);
            const float* src = xrow + nit * 256 + lane * 8;
            cp16(&ring[warp][ns][lane * 2],     src);
            cp16(&ring[warp][ns][lane * 2 + 1], src + 4);
        }
        cp_commit();  // tail commits empty groups, keeping wait counts aligned

        // partial scores for this lane's segment, all heads
        float p[NH];
#pragma unroll
        for (int h = 0; h < NH; h++) {
            float a;
            a = xv0.x * wq0[h].x;
            a = fmaf(xv0.y, wq0[h].y, a);
            a = fmaf(xv0.z, wq0[h].z, a);
            a = fmaf(xv0.w, wq0[h].w, a);
            a = fmaf(xv1.x, wq1[h].x, a);
            a = fmaf(xv1.y, wq1[h].y, a);
            a = fmaf(xv1.z, wq1[h].z, a);
            a = fmaf(xv1.w, wq1[h].w, a);
            p[h] = a;
        }

        // ---- specialized butterfly reduction over the 16-lane half (5 shfls) ----
        // step 1 (xor 8): lanes with b3=0 keep heads {0,1}, b3=1 keep {2,3}
        float s1 = b3 ? p[0] : p[2];
        float r1 = __shfl_xor_sync(0xffffffffu, s1, 8);
        float q0 = (b3 ? p[2] : p[0]) + r1;          // head 2*b3
        float s2 = b3 ? p[1] : p[3];
        float r2 = __shfl_xor_sync(0xffffffffu, s2, 8);
        float q1 = (b3 ? p[3] : p[1]) + r2;          // head 2*b3+1
        // step 2 (xor 4): keep head 2*b3 + b2
        float s3 = b2 ? q0 : q1;
        float r3 = __shfl_xor_sync(0xffffffffu, s3, 4);
        float v  = (b2 ? q1 : q0) + r3;
        // steps 3,4: plain butterfly within the 4-lane head group
        v += __shfl_xor_sync(0xffffffffu, v, 2);
        v += __shfl_xor_sync(0xffffffffu, v, 1);
        // v = full score of head (2*b3+b2) for this half's segment, at all 4 group lanes

        // leaky_relu -> exp, ONE per lane (no max subtraction: |score| <~ 15, fp32-safe)
        float e = __expf(fmaxf(v, 0.2f * v));

        // allgather e across the 4 head groups (3 shfls)
        float g1 = __shfl_xor_sync(0xffffffffu, e, 4);
        float ea = b2 ? g1 : e;     // head 2*b3
        float eb = b2 ? e  : g1;    // head 2*b3+1
        float g2 = __shfl_xor_sync(0xffffffffu, ea, 8);
        float g3 = __shfl_xor_sync(0xffffffffu, eb, 8);
        float e0 = b3 ? g2 : ea;
        float e1 = b3 ? g3 : eb;
        float e2 = b3 ? ea : g2;
        float e3 = b3 ? eb : g3;
        float ev[NH] = {e0, e1, e2, e3};

#pragma unroll
        for (int h = 0; h < NH; h++) {
            float eh = ev[h];
            dsum[h] += eh;
            xb0[h].x = fmaf(eh, xv0.x, xb0[h].x);
            xb0[h].y = fmaf(eh, xv0.y, xb0[h].y);
            xb0[h].z = fmaf(eh, xv0.z, xb0[h].z);
            xb0[h].w = fmaf(eh, xv0.w, xb0[h].w);
            xb1[h].x = fmaf(eh, xv1.x, xb1[h].x);
            xb1[h].y = fmaf(eh, xv1.y, xb1[h].y);
            xb1[h].z = fmaf(eh, xv1.z, xb1[h].z);
            xb1[h].w = fmaf(eh, xv1.w, xb1[h].w);
        }
    }

    // combine the two halves (they handled even/odd segments)
#pragma unroll
    for (int h = 0; h < NH; h++) {
        dsum[h] += __shfl_xor_sync(0xffffffffu, dsum[h], 16);
        xb0[h].x += __shfl_xor_sync(0xffffffffu, xb0[h].x, 16);
        xb0[h].y += __shfl_xor_sync(0xffffffffu, xb0[h].y, 16);
        xb0[h].z += __shfl_xor_sync(0xffffffffu, xb0[h].z, 16);
        xb0[h].w += __shfl_xor_sync(0xffffffffu, xb0[h].w, 16);
        xb1[h].x += __shfl_xor_sync(0xffffffffu, xb1[h].x, 16);
        xb1[h].y += __shfl_xor_sync(0xffffffffu, xb1[h].y, 16);
        xb1[h].z += __shfl_xor_sync(0xffffffffu, xb1[h].z, 16);
        xb1[h].w += __shfl_xor_sync(0xffffffffu, xb1[h].w, 16);
    }

    // stage normalized xbar into (now-idle) ring space: 512 floats per warp
    float* sx = (float*)&ring[warp][0][0];
    __syncwarp();   // everyone done reading the ring
    if (half == 0) {
#pragma unroll
        for (int h = 0; h < NH; h++) {
            float inv = 1.0f / dsum[h];
            float4 v0 = xb0[h], v1 = xb1[h];
            v0.x *= inv; v0.y *= inv; v0.z *= inv; v0.w *= inv;
            v1.x *= inv; v1.y *= inv; v1.z *= inv; v1.w *= inv;
            float4* dst = (float4*)(sx + h * IDIM + p16 * 8);
            dst[0] = v0;
            dst[1] = v1;
        }
    }
    __syncwarp();

    // epilogue GEMV: pooled[h,o] = sum_i xbarN[h,i] * W[h,i,o]
    const int h2 = lane >> 3;
    const int cb = lane & 7;
    const float4* Wv = (const float4*)W + (size_t)h2 * IDIM * (PD / 4) + cb * 2;
    const float* sxh = sx + h2 * IDIM;
    float4 a0 = make_float4(0.f, 0.f, 0.f, 0.f);
    float4 a1 = make_float4(0.f, 0.f, 0.f, 0.f);
#pragma unroll 8
    for (int i = 0; i < IDIM; i++) {
        float xv = sxh[i];                       // broadcast within 8-lane group
        float4 w0 = Wv[i * (PD / 4)];
        float4 w1 = Wv[i * (PD / 4) + 1];
        a0.x = fmaf(xv, w0.x, a0.x);
        a0.y = fmaf(xv, w0.y, a0.y);
        a0.z = fmaf(xv, w0.z, a0.z);
        a0.w = fmaf(xv, w0.w, a0.w);
        a1.x = fmaf(xv, w1.x, a1.x);
        a1.y = fmaf(xv, w1.y, a1.y);
        a1.z = fmaf(xv, w1.z, a1.z);
        a1.w = fmaf(xv, w1.w, a1.w);
    }
    float4* op = (float4*)(out + (size_t)row * OUTD + h2 * PD + cb * 8);
    op[0] = a0;
    op[1] = a1;
}

extern "C" void kernel_launch(void* const* d_in, const int* in_sizes, int n_in,
                              void* d_out, int out_size) {
    // inputs: x [N, 12800], W [4,128,64], q [4,64] — identify defensively by size
    const float* x = (const float*)d_in[0];
    const float* W = (const float*)d_in[1];
    const float* q = (const float*)d_in[2];
    for (int i = 0; i < n_in && i < 3; i++) {
        if (in_sizes[i] == N_ROWS * SPLIT * IDIM) x = (const float*)d_in[i];
        else if (in_sizes[i] == NH * IDIM * PD)   W = (const float*)d_in[i];
        else if (in_sizes[i] == NH * PD)          q = (const float*)d_in[i];
    }
    float* out = (float*)d_out;

    wq_kernel<<<1, 512>>>(W, q);
    attn_kernel<<<N_ROWS / NWARP, NWARP * 32>>>(x, W, out);
}